// round 2
// baseline (speedup 1.0000x reference)
#include <cuda_runtime.h>

// ---------------- problem constants ----------------
#define T_STEPS 512
#define BSZ     256
#define NINP    128
#define NHID    512
#define NOUT    10
#define KTOT    1152            // NINP + 2*NHID
#define DT      0.042f
#define GAMMA_C 2.7f
#define EPS_C   4.7f

// ---------------- launch geometry -------------------
#define GRIDN   128             // 8 output tiles (128x128) x 16 K-slices
#define NTH     256
#define KSLICE  72              // 1152 / 16
#define NCHUNK  9               // 72 / 8

// ---------------- persistent scratch ----------------
__device__ float g_hy[BSZ * NHID];                 // 512 KB
__device__ float g_hz[BSZ * NHID];                 // 512 KB
__device__ float g_part[16 * 8 * 128 * 128];       // 8 MB partials [ks][tile][r*128+c]
__device__ unsigned int g_count;
__device__ unsigned int g_phase;

// Grid-wide barrier (all GRIDN CTAs co-resident: 128 CTAs <= 148 SMs, 1/SM).
__device__ __forceinline__ void gbar(unsigned int &target) {
    __syncthreads();
    target += 1u;
    if (threadIdx.x == 0) {
        __threadfence();                            // release our writes (gpu scope)
        unsigned int a = atomicAdd(&g_count, 1u);
        if (a == GRIDN - 1u) {
            atomicExch(&g_count, 0u);
            __threadfence();
            atomicExch(&g_phase, target);           // release barrier
        } else {
            while (atomicAdd(&g_phase, 0u) < target) { }
        }
        __threadfence();                            // acquire (CCTL.IVALL -> L1 inval)
    }
    __syncthreads();
}

// Load one 8-K chunk of A (gathered from x/hz/hy) and B (W) into registers.
__device__ __forceinline__ void load_chunk(
    int t, int kbase, int row0, int col0, int tid,
    const float* __restrict__ x, const float* __restrict__ W,
    float rA[4], float rB[4])
{
#pragma unroll
    for (int i = 0; i < 4; i++) {
        int idx  = i * NTH + tid;
        // A element: As[kloc][row], 8 consecutive threads walk k (coalesced 32B)
        int kloc = idx & 7;
        int row  = idx >> 3;
        int k    = kbase + kloc;
        int b_   = row0 + row;
        float v;
        if (k < NINP)
            v = __ldg(x + ((size_t)t * BSZ + b_) * NINP + k);
        else if (k < NINP + NHID)
            v = __ldcg(g_hz + b_ * NHID + (k - NINP));
        else
            v = __ldcg(g_hy + b_ * NHID + (k - NINP - NHID));
        rA[i] = v;
        // B element: Bs[kloc][col], 128 consecutive threads walk col (coalesced)
        int col   = idx & 127;
        int klocb = idx >> 7;
        rB[i] = __ldg(W + (size_t)(kbase + klocb) * NHID + col0 + col);
    }
}

__global__ void __launch_bounds__(NTH, 1)
cornn_persistent(const float* __restrict__ x, const float* __restrict__ W,
                 const float* __restrict__ bias, const float* __restrict__ Wout,
                 const float* __restrict__ bout, float* __restrict__ out)
{
    const int tid = threadIdx.x;
    const int cta = blockIdx.x;

    // Phase counter may carry over from previous launches; all threads see the
    // same stable value at launch start (launches serialized on the stream).
    unsigned int target = *((volatile unsigned int*)&g_phase);

    // -------- init: zero state (fresh every launch -> deterministic) --------
    {
        const float4 z = make_float4(0.f, 0.f, 0.f, 0.f);
        int i = cta * NTH + tid;                    // 32768 threads, 32768 float4s
        ((float4*)g_hy)[i] = z;
        ((float4*)g_hz)[i] = z;
    }
    gbar(target);

    // -------- tiling: cta = tile*16 + ks --------
    const int tile = cta >> 4;                      // 0..7  (2 B-tiles x 4 H-tiles)
    const int ks   = cta & 15;                      // 0..15 K-slices
    const int row0 = (tile >> 2) << 7;              // B origin
    const int col0 = (tile & 3)  << 7;              // H origin
    const int k0   = ks * KSLICE;
    const int tx   = tid & 15,  ty  = tid >> 4;
    const int tx8  = tx << 3,   ty8 = ty << 3;

    __shared__ __align__(16) float As[8][132];      // +4 pad: conflict-free strided writes
    __shared__ __align__(16) float Bs[8][128];

    float* mypart = g_part + (size_t)(ks * 8 + tile) * 16384;

    for (int t = 0; t < T_STEPS; t++) {
        // ---------------- phase 1: partial GEMM ----------------
        float acc[8][8];
#pragma unroll
        for (int i = 0; i < 8; i++)
#pragma unroll
            for (int j = 0; j < 8; j++) acc[i][j] = 0.f;

        float rA[4], rB[4];
        load_chunk(t, k0, row0, col0, tid, x, W, rA, rB);

        for (int c = 0; c < NCHUNK; c++) {
            // stage current chunk to smem
#pragma unroll
            for (int i = 0; i < 4; i++) {
                int idx = i * NTH + tid;
                As[idx & 7][idx >> 3]   = rA[i];
                Bs[idx >> 7][idx & 127] = rB[i];
            }
            __syncthreads();
            // prefetch next chunk (global latency hidden under compute)
            if (c + 1 < NCHUNK)
                load_chunk(t, k0 + (c + 1) * 8, row0, col0, tid, x, W, rA, rB);

#pragma unroll
            for (int k = 0; k < 8; k++) {
                float4 a0 = *(const float4*)&As[k][ty8];
                float4 a1 = *(const float4*)&As[k][ty8 + 4];
                float4 b0 = *(const float4*)&Bs[k][tx8];
                float4 b1 = *(const float4*)&Bs[k][tx8 + 4];
                float av[8] = {a0.x, a0.y, a0.z, a0.w, a1.x, a1.y, a1.z, a1.w};
                float bv[8] = {b0.x, b0.y, b0.z, b0.w, b1.x, b1.y, b1.z, b1.w};
#pragma unroll
                for (int i = 0; i < 8; i++)
#pragma unroll
                    for (int j = 0; j < 8; j++)
                        acc[i][j] = fmaf(av[i], bv[j], acc[i][j]);
            }
            __syncthreads();
        }

        // write partials (L2 resident, bypass L1)
#pragma unroll
        for (int i = 0; i < 8; i++) {
            float4 v0 = make_float4(acc[i][0], acc[i][1], acc[i][2], acc[i][3]);
            float4 v1 = make_float4(acc[i][4], acc[i][5], acc[i][6], acc[i][7]);
            float* p = mypart + (ty8 + i) * 128 + tx8;
            __stcg((float4*)p,       v0);
            __stcg((float4*)(p + 4), v1);
        }
        gbar(target);

        // ---------------- phase 2: reduce + tanh + oscillator update ----------------
        {
            int g       = cta * NTH + tid;          // float4 id 0..32767
            int tileIdx = g >> 12;                  // 4096 float4 per tile
            int off4    = g & 4095;
            int r       = off4 >> 5;
            int c4      = off4 & 31;
            int b_      = ((tileIdx >> 2) << 7) + r;
            int h       = ((tileIdx & 3)  << 7) + (c4 << 2);

            float4 s = make_float4(0.f, 0.f, 0.f, 0.f);
#pragma unroll
            for (int p = 0; p < 16; p++) {
                float4 v = __ldcg((const float4*)g_part + (size_t)(p * 8 + tileIdx) * 4096 + off4);
                s.x += v.x; s.y += v.y; s.z += v.z; s.w += v.w;
            }
            float4 bb = *(const float4*)&bias[h];
            int sidx  = (b_ * NHID + h) >> 2;
            float4 hz = __ldcg((const float4*)g_hz + sidx);
            float4 hy = __ldcg((const float4*)g_hy + sidx);

            float pre;
            pre  = tanhf(s.x + bb.x);
            hz.x += DT * (pre - GAMMA_C * hy.x - EPS_C * hz.x);  hy.x += DT * hz.x;
            pre  = tanhf(s.y + bb.y);
            hz.y += DT * (pre - GAMMA_C * hy.y - EPS_C * hz.y);  hy.y += DT * hz.y;
            pre  = tanhf(s.z + bb.z);
            hz.z += DT * (pre - GAMMA_C * hy.z - EPS_C * hz.z);  hy.z += DT * hz.z;
            pre  = tanhf(s.w + bb.w);
            hz.w += DT * (pre - GAMMA_C * hy.w - EPS_C * hz.w);  hy.w += DT * hz.w;

            __stcg((float4*)g_hz + sidx, hz);
            __stcg((float4*)g_hy + sidx, hy);
        }
        gbar(target);
    }

    // ---------------- final projection: out = hy @ Wout + bout ----------------
    {
        int g = cta * NTH + tid;
        if (g < BSZ * NOUT) {
            int b_ = g / NOUT;
            int o  = g - b_ * NOUT;
            float s = __ldg(&bout[o]);
            const float* hyrow = g_hy + b_ * NHID;
#pragma unroll 8
            for (int h = 0; h < NHID; h++)
                s = fmaf(__ldcg(&hyrow[h]), __ldg(&Wout[h * NOUT + o]), s);
            out[g] = s;
        }
    }
}

extern "C" void kernel_launch(void* const* d_in, const int* in_sizes, int n_in,
                              void* d_out, int out_size)
{
    const float *x = nullptr, *W = nullptr, *b = nullptr, *Wout = nullptr, *bout = nullptr;
    for (int i = 0; i < n_in; i++) {
        switch (in_sizes[i]) {
            case T_STEPS * BSZ * NINP: x    = (const float*)d_in[i]; break;  // 16777216
            case KTOT * NHID:          W    = (const float*)d_in[i]; break;  // 589824
            case NHID:                 b    = (const float*)d_in[i]; break;  // 512
            case NHID * NOUT:          Wout = (const float*)d_in[i]; break;  // 5120
            case NOUT:                 bout = (const float*)d_in[i]; break;  // 10
            default: break;
        }
    }
    cornn_persistent<<<GRIDN, NTH>>>(x, W, b, Wout, bout, (float*)d_out);
}

// round 6
// speedup vs baseline: 1.1924x; 1.1924x over previous
#include <cuda_runtime.h>
#include <cuda_bf16.h>
#include <cstdint>

// ---------------- problem constants ----------------
#define T_STEPS 512
#define BSZ     256
#define NINP    128
#define NHID    512
#define NOUT    10
#define DT      0.042f
#define GAMMA_C 2.7f
#define EPS_C   4.7f

// ---------------- geometry ----------------
#define NSLICE  9               // K split: 1152 = 9 * 128
#define NTILE   8               // 2 row-tiles(128) x 4 col-tiles(128)
#define GRIDN   72              // 8 * 9 persistent CTAs
#define NTH     256

// ---------------- smem layout (bf16 [128][136] padded tiles) ----------------
#define ROWW    68              // row stride in 32-bit words (136 bf16) -> conflict-free frags
#define TILE_B  (128 * ROWW * 4)     // 34816 bytes per buffer
#define OFF_AHI 0
#define OFF_ALO (TILE_B)
#define OFF_BHI (2 * TILE_B)
#define OFF_BLO (3 * TILE_B)
#define SMEM_TOTAL (4 * TILE_B)      // 139264 B

// ---------------- persistent device scratch ----------------
__device__ float g_hy[BSZ * NHID];
__device__ float g_hz[BSZ * NHID];
__device__ float g_part[NSLICE * NTILE * 128 * 128];   // 4.5 MB fp32 partials
__device__ unsigned int g_count;
__device__ unsigned int g_phase;

// Grid-wide barrier (72 CTAs, all co-resident: 1 CTA/SM)
static __device__ __forceinline__ void gbar(unsigned int &target) {
    __syncthreads();
    target += 1u;
    if (threadIdx.x == 0) {
        __threadfence();
        unsigned int a = atomicAdd(&g_count, 1u);
        if (a == GRIDN - 1u) {
            atomicExch(&g_count, 0u);
            __threadfence();
            atomicExch(&g_phase, target);
        } else {
            while (atomicAdd(&g_phase, 0u) < target) { }
        }
        __threadfence();
    }
    __syncthreads();
}

static __device__ __forceinline__ uint32_t pack_bf16x2(float lo, float hi) {
    __nv_bfloat16 a = __float2bfloat16(lo);
    __nv_bfloat16 b = __float2bfloat16(hi);
    uint16_t ua = *(uint16_t*)&a, ub = *(uint16_t*)&b;
    return (uint32_t)ua | ((uint32_t)ub << 16);
}

static __device__ __forceinline__ void mma16816(
    float c[4], uint32_t a0, uint32_t a1, uint32_t a2, uint32_t a3,
    uint32_t b0, uint32_t b1)
{
    asm volatile(
        "mma.sync.aligned.m16n8k16.row.col.f32.bf16.bf16.f32 "
        "{%0,%1,%2,%3}, {%4,%5,%6,%7}, {%8,%9}, {%0,%1,%2,%3};"
        : "+f"(c[0]), "+f"(c[1]), "+f"(c[2]), "+f"(c[3])
        : "r"(a0), "r"(a1), "r"(a2), "r"(a3), "r"(b0), "r"(b1));
}

__global__ void __launch_bounds__(NTH, 1)
cornn_mma(const float* __restrict__ x, const float* __restrict__ W,
          const float* __restrict__ bias, const float* __restrict__ Wout,
          const float* __restrict__ bout, float* __restrict__ out)
{
    extern __shared__ char smem[];
    uint32_t* const sAhi = (uint32_t*)(smem + OFF_AHI);
    uint32_t* const sAlo = (uint32_t*)(smem + OFF_ALO);
    uint32_t* const sBhi = (uint32_t*)(smem + OFF_BHI);
    uint32_t* const sBlo = (uint32_t*)(smem + OFF_BLO);

    const int tid = threadIdx.x;
    const int cta = blockIdx.x;

    unsigned int target = *((volatile unsigned int*)&g_phase);

    // ---- tiling ----
    const int slice = cta % NSLICE;          // 0..8  -> k0 = slice*128
    const int tile  = cta / NSLICE;          // 0..7
    const int row0  = (tile >> 2) << 7;      // batch-row origin (0 or 128)
    const int col0  = (tile & 3)  << 7;      // hidden-col origin
    const int k0    = slice << 7;

    // warp layout: 4x2 grid of 32x64 warp tiles
    const int wid = tid >> 5;
    const int lane = tid & 31;
    const int g_  = lane >> 2;               // 0..7
    const int tg  = lane & 3;                // 0..3
    const int wr  = wid >> 1;                // 0..3 -> m rows wr*32
    const int wc  = wid & 1;                 // 0..1 -> n cols wc*64

    // ---- zero recurrent state ----
    {
        const float4 z = make_float4(0.f, 0.f, 0.f, 0.f);
        for (int g = cta * NTH + tid; g < (BSZ * NHID) / 4; g += GRIDN * NTH) {
            ((float4*)g_hy)[g] = z;
            ((float4*)g_hz)[g] = z;
        }
    }

    // ---- one-time: W slice -> Bhi/Blo, stored TRANSPOSED [n][k] padded ----
#pragma unroll 4
    for (int i = 0; i < 64; i++) {
        int idx = i * NTH + tid;             // 16384 elems, n fast (coalesced gmem)
        int n   = idx & 127;
        int kk  = idx >> 7;
        float w = __ldg(W + (size_t)(k0 + kk) * NHID + col0 + n);
        __nv_bfloat16 hi = __float2bfloat16(w);
        float rem = w - __bfloat162float(hi);
        __nv_bfloat16 lo = __float2bfloat16(rem);
        // bf16 element store at [n][kk]
        ((__nv_bfloat16*)sBhi)[n * (2 * ROWW) + kk] = hi;
        ((__nv_bfloat16*)sBlo)[n * (2 * ROWW) + kk] = lo;
    }
    gbar(target);

    float* mypart = g_part + (size_t)(slice * NTILE + tile) * 16384;

    // A source for this K slice (x_t handled separately; hz/hy 128-wide aligned)
    const float* srcState = (slice == 0) ? nullptr
                          : (slice <= 4) ? (g_hz + row0 * NHID + (slice - 1) * 128)
                                         : (g_hy + row0 * NHID + (slice - 5) * 128);

    for (int t = 0; t < T_STEPS; t++) {
        // ---------- stage A: fp32 -> bf16 hi/lo [m][k] padded ----------
        {
            const float* srcX = x + ((size_t)t * BSZ + row0) * NINP;
#pragma unroll 4
            for (int i = 0; i < 32; i++) {
                int idx = i * NTH + tid;      // 8192 float2 pairs
                int row = idx >> 6;
                int kw  = idx & 63;           // word (pair) index in k
                float2 v;
                if (slice == 0) v = *(const float2*)(srcX + row * NINP + kw * 2);
                else            v = __ldcg((const float2*)(srcState + row * NHID + kw * 2));
                float h0f = __bfloat162float(__float2bfloat16(v.x));
                float h1f = __bfloat162float(__float2bfloat16(v.y));
                int wi = row * ROWW + kw;
                sAhi[wi] = pack_bf16x2(h0f, h1f);
                sAlo[wi] = pack_bf16x2(v.x - h0f, v.y - h1f);
            }
        }
        __syncthreads();

        // ---------- 3-pass split GEMM on tensor pipe (mma.sync bf16) ----------
        float acc[2][8][4];
#pragma unroll
        for (int mt = 0; mt < 2; mt++)
#pragma unroll
            for (int nt = 0; nt < 8; nt++)
#pragma unroll
                for (int q = 0; q < 4; q++) acc[mt][nt][q] = 0.f;

#pragma unroll 1
        for (int p = 0; p < 3; p++) {
            const uint32_t* A32 = (p == 2) ? sAlo : sAhi;
            const uint32_t* B32 = (p == 1) ? sBlo : sBhi;
#pragma unroll
            for (int kk8 = 0; kk8 < 8; kk8++) {   // k16 blocks
                const int kw = kk8 * 8 + tg;
                uint32_t a[2][4];
#pragma unroll
                for (int mt = 0; mt < 2; mt++) {
                    int m0 = wr * 32 + mt * 16;
                    a[mt][0] = A32[(m0 + g_)     * ROWW + kw];
                    a[mt][1] = A32[(m0 + g_ + 8) * ROWW + kw];
                    a[mt][2] = A32[(m0 + g_)     * ROWW + kw + 4];
                    a[mt][3] = A32[(m0 + g_ + 8) * ROWW + kw + 4];
                }
#pragma unroll
                for (int nt = 0; nt < 8; nt++) {
                    int n = wc * 64 + nt * 8 + g_;
                    uint32_t b0 = B32[n * ROWW + kw];
                    uint32_t b1 = B32[n * ROWW + kw + 4];
                    mma16816(acc[0][nt], a[0][0], a[0][1], a[0][2], a[0][3], b0, b1);
                    mma16816(acc[1][nt], a[1][0], a[1][1], a[1][2], a[1][3], b0, b1);
                }
            }
        }

        // ---------- write partials (fp32, L2-resident) ----------
#pragma unroll
        for (int mt = 0; mt < 2; mt++) {
#pragma unroll
            for (int nt = 0; nt < 8; nt++) {
                int m = wr * 32 + mt * 16 + g_;
                int n = wc * 64 + nt * 8 + tg * 2;
                __stcg((float2*)(mypart + m * 128 + n),
                       make_float2(acc[mt][nt][0], acc[mt][nt][1]));
                __stcg((float2*)(mypart + (m + 8) * 128 + n),
                       make_float2(acc[mt][nt][2], acc[mt][nt][3]));
            }
        }
        gbar(target);

        // ---------- reduce partials + tanh + oscillator update ----------
        {
#pragma unroll
            for (int it = 0; it < 2; it++) {
                int g = it * (GRIDN * NTH) + cta * NTH + tid;   // float4 index
                if (g < (BSZ * NHID) / 4) {
                    int b_ = g >> 7;
                    int h  = (g & 127) << 2;
                    int tl = ((b_ >> 7) << 2) + (h >> 7);
                    int ro = b_ & 127, co = h & 127;
                    const float* pp = g_part + (size_t)tl * 16384 + ro * 128 + co;
                    float4 s = make_float4(0.f, 0.f, 0.f, 0.f);
#pragma unroll
                    for (int sl = 0; sl < NSLICE; sl++) {
                        float4 v = __ldcg((const float4*)(pp + (size_t)sl * NTILE * 16384));
                        s.x += v.x; s.y += v.y; s.z += v.z; s.w += v.w;
                    }
                    float4 bb = *(const float4*)&bias[h];
                    float4 hz = __ldcg((const float4*)g_hz + g);
                    float4 hy = __ldcg((const float4*)g_hy + g);
                    float pre;
                    pre = tanhf(s.x + bb.x); hz.x += DT * (pre - GAMMA_C * hy.x - EPS_C * hz.x); hy.x += DT * hz.x;
                    pre = tanhf(s.y + bb.y); hz.y += DT * (pre - GAMMA_C * hy.y - EPS_C * hz.y); hy.y += DT * hz.y;
                    pre = tanhf(s.z + bb.z); hz.z += DT * (pre - GAMMA_C * hy.z - EPS_C * hz.z); hy.z += DT * hz.z;
                    pre = tanhf(s.w + bb.w); hz.w += DT * (pre - GAMMA_C * hy.w - EPS_C * hz.w); hy.w += DT * hz.w;
                    __stcg((float4*)g_hz + g, hz);
                    __stcg((float4*)g_hy + g, hy);
                }
            }
        }
        gbar(target);
    }

    // ---------- final projection: out = hy @ Wout + bout ----------
    {
        int g = cta * NTH + tid;
        if (g < BSZ * NOUT) {
            int b_ = g / NOUT;
            int o  = g - b_ * NOUT;
            float s = __ldg(&bout[o]);
            const float* hyrow = g_hy + b_ * NHID;
#pragma unroll 8
            for (int h = 0; h < NHID; h++)
                s = fmaf(__ldcg(&hyrow[h]), __ldg(&Wout[h * NOUT + o]), s);
            out[g] = s;
        }
    }
}

extern "C" void kernel_launch(void* const* d_in, const int* in_sizes, int n_in,
                              void* d_out, int out_size)
{
    const float *x = nullptr, *W = nullptr, *b = nullptr, *Wout = nullptr, *bout = nullptr;
    for (int i = 0; i < n_in; i++) {
        switch (in_sizes[i]) {
            case T_STEPS * BSZ * NINP:      x    = (const float*)d_in[i]; break;
            case (NINP + 2 * NHID) * NHID:  W    = (const float*)d_in[i]; break;
            case NHID:                      b    = (const float*)d_in[i]; break;
            case NHID * NOUT:               Wout = (const float*)d_in[i]; break;
            case NOUT:                      bout = (const float*)d_in[i]; break;
            default: break;
        }
    }
    cudaFuncSetAttribute(cornn_mma, cudaFuncAttributeMaxDynamicSharedMemorySize, SMEM_TOTAL);
    cornn_mma<<<GRIDN, NTH, SMEM_TOTAL>>>(x, W, b, Wout, bout, (float*)d_out);
}

// round 8
// speedup vs baseline: 1.2957x; 1.0867x over previous
#include <cuda_runtime.h>
#include <cuda_bf16.h>
#include <cstdint>

// ---------------- problem constants ----------------
#define T_STEPS 512
#define BSZ     256
#define NINP    128
#define NHID    512
#define NOUT    10
#define DT      0.042f
#define GAMMA_C 2.7f
#define EPS_C   4.7f

// ---------------- geometry ----------------
#define NSLICE  9               // K split: 1152 = 9 * 128
#define NTILE   8               // 2 row-tiles(128) x 4 col-tiles(128)
#define GRIDN   72              // 8 * 9 persistent CTAs
#define NTH     256

// ---------------- smem layout (bf16 [128][136] padded tiles) ----------------
#define ROWW    68              // row stride in 32-bit words (136 bf16) -> conflict-free frags
#define TILE_B  (128 * ROWW * 4)     // 34816 bytes per buffer
#define OFF_AHI 0
#define OFF_ALO (TILE_B)
#define OFF_BHI (2 * TILE_B)
#define OFF_BLO (3 * TILE_B)
#define SMEM_TOTAL (4 * TILE_B)      // 139264 B

// ---------------- persistent device scratch ----------------
__device__ float g_hy[BSZ * NHID];
__device__ float g_hz[BSZ * NHID];
__device__ float g_part[NSLICE * NTILE * 128 * 128];   // 4.5 MB fp32 partials
__device__ unsigned int g_count;
__device__ unsigned int g_phase;

// ---------------- release/acquire primitives (no fence.sc, no RMW polling) ----
static __device__ __forceinline__ unsigned int ld_acquire_gpu(const unsigned int* p) {
    unsigned int v;
    asm volatile("ld.global.acquire.gpu.u32 %0, [%1];" : "=r"(v) : "l"(p) : "memory");
    return v;
}
static __device__ __forceinline__ unsigned int atom_add_release_gpu(unsigned int* p, unsigned int v) {
    unsigned int o;
    asm volatile("atom.global.add.release.gpu.u32 %0, [%1], %2;" : "=r"(o) : "l"(p), "r"(v) : "memory");
    return o;
}
static __device__ __forceinline__ void st_release_gpu(unsigned int* p, unsigned int v) {
    asm volatile("st.global.release.gpu.u32 [%0], %1;" :: "l"(p), "r"(v) : "memory");
}
static __device__ __forceinline__ void st_relaxed_gpu(unsigned int* p, unsigned int v) {
    asm volatile("st.global.relaxed.gpu.u32 [%0], %1;" :: "l"(p), "r"(v) : "memory");
}

// Grid-wide barrier (72 CTAs, all co-resident: 1 CTA/SM).
// Arrive: release-atomic (orders all prior CTA writes via bar.sync transitivity).
// Wait: acquire-LOAD polling (no L2 atomic-ALU serialization).
static __device__ __forceinline__ void gbar(unsigned int &target) {
    __syncthreads();
    target += 1u;
    if (threadIdx.x == 0) {
        unsigned int a = atom_add_release_gpu(&g_count, 1u);
        if (a == GRIDN - 1u) {
            st_relaxed_gpu(&g_count, 0u);          // reset before release; ordered by release below
            st_release_gpu(&g_phase, target);      // release barrier
        } else {
            while (ld_acquire_gpu(&g_phase) < target) { }
        }
    }
    __syncthreads();
}

static __device__ __forceinline__ uint32_t pack_bf16x2(float lo, float hi) {
    __nv_bfloat16 a = __float2bfloat16(lo);
    __nv_bfloat16 b = __float2bfloat16(hi);
    uint16_t ua = *(uint16_t*)&a, ub = *(uint16_t*)&b;
    return (uint32_t)ua | ((uint32_t)ub << 16);
}

static __device__ __forceinline__ void mma16816(
    float c[4], uint32_t a0, uint32_t a1, uint32_t a2, uint32_t a3,
    uint32_t b0, uint32_t b1)
{
    asm volatile(
        "mma.sync.aligned.m16n8k16.row.col.f32.bf16.bf16.f32 "
        "{%0,%1,%2,%3}, {%4,%5,%6,%7}, {%8,%9}, {%0,%1,%2,%3};"
        : "+f"(c[0]), "+f"(c[1]), "+f"(c[2]), "+f"(c[3])
        : "r"(a0), "r"(a1), "r"(a2), "r"(a3), "r"(b0), "r"(b1));
}

__global__ void __launch_bounds__(NTH, 1)
cornn_mma(const float* __restrict__ x, const float* __restrict__ W,
          const float* __restrict__ bias, const float* __restrict__ Wout,
          const float* __restrict__ bout, float* __restrict__ out)
{
    extern __shared__ char smem[];
    uint32_t* const sAhi = (uint32_t*)(smem + OFF_AHI);
    uint32_t* const sAlo = (uint32_t*)(smem + OFF_ALO);
    uint32_t* const sBhi = (uint32_t*)(smem + OFF_BHI);
    uint32_t* const sBlo = (uint32_t*)(smem + OFF_BLO);

    const int tid = threadIdx.x;
    const int cta = blockIdx.x;

    unsigned int target = *((volatile unsigned int*)&g_phase);

    // ---- tiling ----
    const int slice = cta % NSLICE;          // 0..8  -> k0 = slice*128
    const int tile  = cta / NSLICE;          // 0..7
    const int row0  = (tile >> 2) << 7;      // batch-row origin (0 or 128)
    const int col0  = (tile & 3)  << 7;      // hidden-col origin
    const int k0    = slice << 7;

    // warp layout: 4x2 grid of 32x64 warp tiles
    const int wid = tid >> 5;
    const int lane = tid & 31;
    const int g_  = lane >> 2;               // 0..7
    const int tg  = lane & 3;                // 0..3
    const int wr  = wid >> 1;                // 0..3 -> m rows wr*32
    const int wc  = wid & 1;                 // 0..1 -> n cols wc*64

    // ---- zero recurrent state ----
    {
        const float4 z = make_float4(0.f, 0.f, 0.f, 0.f);
        for (int g = cta * NTH + tid; g < (BSZ * NHID) / 4; g += GRIDN * NTH) {
            ((float4*)g_hy)[g] = z;
            ((float4*)g_hz)[g] = z;
        }
    }

    // ---- one-time: W slice -> Bhi/Blo, stored TRANSPOSED [n][k] padded ----
#pragma unroll 4
    for (int i = 0; i < 64; i++) {
        int idx = i * NTH + tid;             // 16384 elems, n fast (coalesced gmem)
        int n   = idx & 127;
        int kk  = idx >> 7;
        float w = __ldg(W + (size_t)(k0 + kk) * NHID + col0 + n);
        __nv_bfloat16 hi = __float2bfloat16(w);
        float rem = w - __bfloat162float(hi);
        __nv_bfloat16 lo = __float2bfloat16(rem);
        ((__nv_bfloat16*)sBhi)[n * (2 * ROWW) + kk] = hi;
        ((__nv_bfloat16*)sBlo)[n * (2 * ROWW) + kk] = lo;
    }
    gbar(target);

    float* mypart = g_part + (size_t)(slice * NTILE + tile) * 16384;

    // A source for this K slice (x_t handled separately; hz/hy 128-wide aligned)
    const float* srcState = (slice == 0) ? nullptr
                          : (slice <= 4) ? (g_hz + row0 * NHID + (slice - 1) * 128)
                                         : (g_hy + row0 * NHID + (slice - 5) * 128);

    for (int t = 0; t < T_STEPS; t++) {
        // ---------- stage A: fp32 -> bf16 hi/lo [m][k] padded ----------
        {
            const float* srcX = x + ((size_t)t * BSZ + row0) * NINP;
#pragma unroll 4
            for (int i = 0; i < 32; i++) {
                int idx = i * NTH + tid;      // 8192 float2 pairs
                int row = idx >> 6;
                int kw  = idx & 63;           // word (pair) index in k
                float2 v;
                if (slice == 0) v = *(const float2*)(srcX + row * NINP + kw * 2);
                else            v = __ldcg((const float2*)(srcState + row * NHID + kw * 2));
                float h0f = __bfloat162float(__float2bfloat16(v.x));
                float h1f = __bfloat162float(__float2bfloat16(v.y));
                int wi = row * ROWW + kw;
                sAhi[wi] = pack_bf16x2(h0f, h1f);
                sAlo[wi] = pack_bf16x2(v.x - h0f, v.y - h1f);
            }
        }
        __syncthreads();

        // ---------- 3-pass split GEMM on tensor pipe (mma.sync bf16) ----------
        float acc[2][8][4];
#pragma unroll
        for (int mt = 0; mt < 2; mt++)
#pragma unroll
            for (int nt = 0; nt < 8; nt++)
#pragma unroll
                for (int q = 0; q < 4; q++) acc[mt][nt][q] = 0.f;

#pragma unroll 1
        for (int p = 0; p < 3; p++) {
            const uint32_t* A32 = (p == 2) ? sAlo : sAhi;
            const uint32_t* B32 = (p == 1) ? sBlo : sBhi;
#pragma unroll
            for (int kk8 = 0; kk8 < 8; kk8++) {   // k16 blocks
                const int kw = kk8 * 8 + tg;
                uint32_t a[2][4];
#pragma unroll
                for (int mt = 0; mt < 2; mt++) {
                    int m0 = wr * 32 + mt * 16;
                    a[mt][0] = A32[(m0 + g_)     * ROWW + kw];
                    a[mt][1] = A32[(m0 + g_ + 8) * ROWW + kw];
                    a[mt][2] = A32[(m0 + g_)     * ROWW + kw + 4];
                    a[mt][3] = A32[(m0 + g_ + 8) * ROWW + kw + 4];
                }
#pragma unroll
                for (int nt = 0; nt < 8; nt++) {
                    int n = wc * 64 + nt * 8 + g_;
                    uint32_t b0 = B32[n * ROWW + kw];
                    uint32_t b1 = B32[n * ROWW + kw + 4];
                    mma16816(acc[0][nt], a[0][0], a[0][1], a[0][2], a[0][3], b0, b1);
                    mma16816(acc[1][nt], a[1][0], a[1][1], a[1][2], a[1][3], b0, b1);
                }
            }
        }

        // ---------- write partials (fp32, L2-resident) ----------
#pragma unroll
        for (int mt = 0; mt < 2; mt++) {
#pragma unroll
            for (int nt = 0; nt < 8; nt++) {
                int m = wr * 32 + mt * 16 + g_;
                int n = wc * 64 + nt * 8 + tg * 2;
                __stcg((float2*)(mypart + m * 128 + n),
                       make_float2(acc[mt][nt][0], acc[mt][nt][1]));
                __stcg((float2*)(mypart + (m + 8) * 128 + n),
                       make_float2(acc[mt][nt][2], acc[mt][nt][3]));
            }
        }
        gbar(target);

        // ---------- reduce partials + tanh + oscillator update ----------
        {
#pragma unroll
            for (int it = 0; it < 2; it++) {
                int g = it * (GRIDN * NTH) + cta * NTH + tid;   // float4 index
                if (g < (BSZ * NHID) / 4) {
                    int b_ = g >> 7;
                    int h  = (g & 127) << 2;
                    int tl = ((b_ >> 7) << 2) + (h >> 7);
                    int ro = b_ & 127, co = h & 127;
                    const float* pp = g_part + (size_t)tl * 16384 + ro * 128 + co;
                    float4 s = make_float4(0.f, 0.f, 0.f, 0.f);
#pragma unroll
                    for (int sl = 0; sl < NSLICE; sl++) {
                        float4 v = __ldcg((const float4*)(pp + (size_t)sl * NTILE * 16384));
                        s.x += v.x; s.y += v.y; s.z += v.z; s.w += v.w;
                    }
                    float4 bb = *(const float4*)&bias[h];
                    float4 hz = __ldcg((const float4*)g_hz + g);
                    float4 hy = __ldcg((const float4*)g_hy + g);
                    float pre;
                    pre = tanhf(s.x + bb.x); hz.x += DT * (pre - GAMMA_C * hy.x - EPS_C * hz.x); hy.x += DT * hz.x;
                    pre = tanhf(s.y + bb.y); hz.y += DT * (pre - GAMMA_C * hy.y - EPS_C * hz.y); hy.y += DT * hz.y;
                    pre = tanhf(s.z + bb.z); hz.z += DT * (pre - GAMMA_C * hy.z - EPS_C * hz.z); hy.z += DT * hz.z;
                    pre = tanhf(s.w + bb.w); hz.w += DT * (pre - GAMMA_C * hy.w - EPS_C * hz.w); hy.w += DT * hz.w;
                    __stcg((float4*)g_hz + g, hz);
                    __stcg((float4*)g_hy + g, hy);
                }
            }
        }
        gbar(target);
    }

    // ---------- final projection: out = hy @ Wout + bout ----------
    {
        int g = cta * NTH + tid;
        if (g < BSZ * NOUT) {
            int b_ = g / NOUT;
            int o  = g - b_ * NOUT;
            float s = __ldg(&bout[o]);
            const float* hyrow = g_hy + b_ * NHID;
#pragma unroll 8
            for (int h = 0; h < NHID; h++)
                s = fmaf(__ldcg(&hyrow[h]), __ldg(&Wout[h * NOUT + o]), s);
            out[g] = s;
        }
    }
}

extern "C" void kernel_launch(void* const* d_in, const int* in_sizes, int n_in,
                              void* d_out, int out_size)
{
    const float *x = nullptr, *W = nullptr, *b = nullptr, *Wout = nullptr, *bout = nullptr;
    for (int i = 0; i < n_in; i++) {
        switch (in_sizes[i]) {
            case T_STEPS * BSZ * NINP:      x    = (const float*)d_in[i]; break;
            case (NINP + 2 * NHID) * NHID:  W    = (const float*)d_in[i]; break;
            case NHID:                      b    = (const float*)d_in[i]; break;
            case NHID * NOUT:               Wout = (const float*)d_in[i]; break;
            case NOUT:                      bout = (const float*)d_in[i]; break;
            default: break;
        }
    }
    cudaFuncSetAttribute(cornn_mma, cudaFuncAttributeMaxDynamicSharedMemorySize, SMEM_TOTAL);
    cornn_mma<<<GRIDN, NTH, SMEM_TOTAL>>>(x, W, b, Wout, bout, (float*)d_out);
}

// round 11
// speedup vs baseline: 1.6785x; 1.2954x over previous
#include <cuda_runtime.h>
#include <cuda_bf16.h>
#include <cstdint>

// ---------------- problem constants ----------------
#define T_STEPS 512
#define BSZ     256
#define NINP    128
#define NHID    512
#define NOUT    10
#define DT      0.042f
#define GAMMA_C 2.7f
#define EPS_C   4.7f

// ---------------- geometry ----------------
#define NSLICE  9               // K split: 1152 = 9 * 128
#define NTILE   8               // 2 row-tiles(128) x 4 col-tiles(128)
#define GRIDN   72              // 8 * 9 persistent CTAs
#define NTH     256

// ---------------- smem layout (bf16 [128][136] padded tiles) ----------------
#define ROWW    68              // row stride in 32-bit words (136 bf16) -> conflict-free frags
#define TILE_B  (128 * ROWW * 4)     // 34816 bytes per buffer
#define OFF_AHI 0
#define OFF_ALO (TILE_B)
#define OFF_BHI (2 * TILE_B)
#define OFF_BLO (3 * TILE_B)
#define SMEM_TOTAL (4 * TILE_B)      // 139264 B

// ---------------- persistent device scratch ----------------
__device__ float g_hy[BSZ * NHID];
__device__ float g_hz[BSZ * NHID];
__device__ float g_part[NSLICE * NTILE * 128 * 128];   // 4.5 MB fp32 partials
__device__ unsigned int g_flags[GRIDN * 32];           // 1 flag / 128B line per CTA

// ---------------- release/acquire primitives ----------------
static __device__ __forceinline__ unsigned int ld_acquire_gpu(const unsigned int* p) {
    unsigned int v;
    asm volatile("ld.global.acquire.gpu.u32 %0, [%1];" : "=r"(v) : "l"(p) : "memory");
    return v;
}
static __device__ __forceinline__ void st_release_gpu(unsigned int* p, unsigned int v) {
    asm volatile("st.global.release.gpu.u32 [%0], %1;" :: "l"(p), "r"(v) : "memory");
}

// Grid-wide barrier: flag-array (no RMW -> no L2 atomic-ALU serialization).
// Arrive: thread 0 release-stores this CTA's flag (bar.sync orders all prior
// CTA writes before it). Wait: threads 0..71 acquire-poll one flag each, in
// parallel; __syncthreads propagates visibility to the whole CTA.
static __device__ __forceinline__ void gbar(unsigned int &target) {
    __syncthreads();
    target += 1u;
    if (threadIdx.x == 0) st_release_gpu(&g_flags[blockIdx.x * 32], target);
    if (threadIdx.x < GRIDN) {
        while (ld_acquire_gpu(&g_flags[threadIdx.x * 32]) < target) { }
    }
    __syncthreads();
}

static __device__ __forceinline__ uint32_t pack_bf16x2(float lo, float hi) {
    __nv_bfloat16 a = __float2bfloat16(lo);
    __nv_bfloat16 b = __float2bfloat16(hi);
    uint16_t ua = *(uint16_t*)&a, ub = *(uint16_t*)&b;
    return (uint32_t)ua | ((uint32_t)ub << 16);
}

static __device__ __forceinline__ uint32_t smem_u32(const void* p) {
    uint32_t a;
    asm("{ .reg .u64 t; cvta.to.shared.u64 t, %1; cvt.u32.u64 %0, t; }" : "=r"(a) : "l"(p));
    return a;
}

static __device__ __forceinline__ void ldsm_x4(
    uint32_t &r0, uint32_t &r1, uint32_t &r2, uint32_t &r3, uint32_t saddr)
{
    asm volatile("ldmatrix.sync.aligned.m8n8.x4.shared.b16 {%0,%1,%2,%3}, [%4];"
        : "=r"(r0), "=r"(r1), "=r"(r2), "=r"(r3) : "r"(saddr));
}

static __device__ __forceinline__ void mma16816(
    float c[4], uint32_t a0, uint32_t a1, uint32_t a2, uint32_t a3,
    uint32_t b0, uint32_t b1)
{
    asm volatile(
        "mma.sync.aligned.m16n8k16.row.col.f32.bf16.bf16.f32 "
        "{%0,%1,%2,%3}, {%4,%5,%6,%7}, {%8,%9}, {%0,%1,%2,%3};"
        : "+f"(c[0]), "+f"(c[1]), "+f"(c[2]), "+f"(c[3])
        : "r"(a0), "r"(a1), "r"(a2), "r"(a3), "r"(b0), "r"(b1));
}

__global__ void __launch_bounds__(NTH, 1)
cornn_mma(const float* __restrict__ x, const float* __restrict__ W,
          const float* __restrict__ bias, const float* __restrict__ Wout,
          const float* __restrict__ bout, float* __restrict__ out)
{
    extern __shared__ char smem[];
    uint32_t* const sAhi = (uint32_t*)(smem + OFF_AHI);
    uint32_t* const sAlo = (uint32_t*)(smem + OFF_ALO);
    uint32_t* const sBhi = (uint32_t*)(smem + OFF_BHI);
    uint32_t* const sBlo = (uint32_t*)(smem + OFF_BLO);

    const int tid = threadIdx.x;
    const int cta = blockIdx.x;

    // flags persist across launches; all equal at launch start (own flag is stable)
    unsigned int target = *((volatile unsigned int*)&g_flags[cta * 32]);

    // ---- tiling ----
    const int slice = cta % NSLICE;          // 0..8  -> k0 = slice*128
    const int tile  = cta / NSLICE;          // 0..7
    const int row0  = (tile >> 2) << 7;      // batch-row origin (0 or 128)
    const int col0  = (tile & 3)  << 7;      // hidden-col origin
    const int k0    = slice << 7;

    // warp layout: 4x2 grid of 32x64 warp tiles
    const int wid  = tid >> 5;
    const int lane = tid & 31;
    const int g_   = lane >> 2;              // 0..7
    const int tg   = lane & 3;               // 0..3
    const int wr   = wid >> 1;               // 0..3 -> m rows wr*32
    const int wc   = wid & 1;                // 0..1 -> n cols wc*64

    // per-lane ldmatrix word offsets (within a tile buffer)
    // A: lanes 0-15 -> row m0+lane, k-lo half; lanes 16-31 -> row m0+lane-16, k-hi half
    const uint32_t aRowW = (uint32_t)((wr * 32 + (lane & 15)) * ROWW + ((lane >> 4) << 2));
    // B: mats (nt, kb), (nt, kb+8), (nt+1, kb), (nt+1, kb+8)
    const uint32_t bRowW = (uint32_t)((wc * 64 + (lane & 7) + ((lane >> 4) << 3)) * ROWW
                                      + (((lane >> 3) & 1) << 2));

    const uint32_t sAhiB = smem_u32(sAhi), sAloB = smem_u32(sAlo);
    const uint32_t sBhiB = smem_u32(sBhi), sBloB = smem_u32(sBlo);

    // ---- zero recurrent state ----
    {
        const float4 z = make_float4(0.f, 0.f, 0.f, 0.f);
        for (int g = cta * NTH + tid; g < (BSZ * NHID) / 4; g += GRIDN * NTH) {
            ((float4*)g_hy)[g] = z;
            ((float4*)g_hz)[g] = z;
        }
    }

    // ---- one-time: W slice -> Bhi/Blo, stored TRANSPOSED [n][k] padded ----
#pragma unroll 4
    for (int i = 0; i < 64; i++) {
        int idx = i * NTH + tid;             // 16384 elems, n fast (coalesced gmem)
        int n   = idx & 127;
        int kk  = idx >> 7;
        float w = __ldg(W + (size_t)(k0 + kk) * NHID + col0 + n);
        __nv_bfloat16 hi = __float2bfloat16(w);
        float rem = w - __bfloat162float(hi);
        __nv_bfloat16 lo = __float2bfloat16(rem);
        ((__nv_bfloat16*)sBhi)[n * (2 * ROWW) + kk] = hi;
        ((__nv_bfloat16*)sBlo)[n * (2 * ROWW) + kk] = lo;
    }
    gbar(target);

    float* mypart = g_part + (size_t)(slice * NTILE + tile) * 16384;

    // A source for this K slice (x_t handled separately; hz/hy 128-wide aligned)
    const float* srcState = (slice == 0) ? nullptr
                          : (slice <= 4) ? (g_hz + row0 * NHID + (slice - 1) * 128)
                                         : (g_hy + row0 * NHID + (slice - 5) * 128);

    for (int t = 0; t < T_STEPS; t++) {
        // ---------- stage A: front-batched float4 loads, fp32 -> bf16 hi/lo ----------
        {
            const float* srcX = x + ((size_t)t * BSZ + row0) * NINP;
#pragma unroll
            for (int half = 0; half < 2; half++) {
                float4 v[8];
#pragma unroll
                for (int i = 0; i < 8; i++) {
                    int idx = (half * 8 + i) * NTH + tid;    // 0..4095 float4
                    int row = idx >> 5;
                    int c4  = idx & 31;
                    v[i] = (slice == 0)
                         ? __ldg ((const float4*)(srcX + row * NINP) + c4)
                         : __ldcg((const float4*)(srcState + row * NHID) + c4);
                }
#pragma unroll
                for (int i = 0; i < 8; i++) {
                    int idx = (half * 8 + i) * NTH + tid;
                    int row = idx >> 5;
                    int c4  = idx & 31;
                    float hx = __bfloat162float(__float2bfloat16(v[i].x));
                    float hy_ = __bfloat162float(__float2bfloat16(v[i].y));
                    float hz_ = __bfloat162float(__float2bfloat16(v[i].z));
                    float hw = __bfloat162float(__float2bfloat16(v[i].w));
                    int wi = row * ROWW + c4 * 2;
                    sAhi[wi]     = pack_bf16x2(hx, hy_);
                    sAhi[wi + 1] = pack_bf16x2(hz_, hw);
                    sAlo[wi]     = pack_bf16x2(v[i].x - hx, v[i].y - hy_);
                    sAlo[wi + 1] = pack_bf16x2(v[i].z - hz_, v[i].w - hw);
                }
            }
        }
        __syncthreads();

        // ---------- 3-pass split GEMM: ldmatrix + mma.sync ----------
        float acc[2][8][4];
#pragma unroll
        for (int mt = 0; mt < 2; mt++)
#pragma unroll
            for (int nt = 0; nt < 8; nt++)
#pragma unroll
                for (int q = 0; q < 4; q++) acc[mt][nt][q] = 0.f;

#pragma unroll 1
        for (int p = 0; p < 3; p++) {
            const uint32_t aB = ((p == 2) ? sAloB : sAhiB) + aRowW * 4;
            const uint32_t bB = ((p == 1) ? sBloB : sBhiB) + bRowW * 4;
#pragma unroll
            for (int kk8 = 0; kk8 < 8; kk8++) {
                const uint32_t kadd = (uint32_t)(kk8 * 32);  // 8 words
                uint32_t a0[4], a1[4];
                ldsm_x4(a0[0], a0[1], a0[2], a0[3], aB + kadd);
                ldsm_x4(a1[0], a1[1], a1[2], a1[3], aB + kadd + 16 * ROWW * 4);
#pragma unroll
                for (int ntp = 0; ntp < 4; ntp++) {
                    uint32_t b[4];
                    ldsm_x4(b[0], b[1], b[2], b[3], bB + kadd + (uint32_t)(ntp * 16 * ROWW * 4));
                    mma16816(acc[0][2*ntp],   a0[0], a0[1], a0[2], a0[3], b[0], b[1]);
                    mma16816(acc[1][2*ntp],   a1[0], a1[1], a1[2], a1[3], b[0], b[1]);
                    mma16816(acc[0][2*ntp+1], a0[0], a0[1], a0[2], a0[3], b[2], b[3]);
                    mma16816(acc[1][2*ntp+1], a1[0], a1[1], a1[2], a1[3], b[2], b[3]);
                }
            }
        }

        // ---------- write partials (fp32, L2-resident) ----------
#pragma unroll
        for (int mt = 0; mt < 2; mt++) {
#pragma unroll
            for (int nt = 0; nt < 8; nt++) {
                int m = wr * 32 + mt * 16 + g_;
                int n = wc * 64 + nt * 8 + tg * 2;
                __stcg((float2*)(mypart + m * 128 + n),
                       make_float2(acc[mt][nt][0], acc[mt][nt][1]));
                __stcg((float2*)(mypart + (m + 8) * 128 + n),
                       make_float2(acc[mt][nt][2], acc[mt][nt][3]));
            }
        }
        gbar(target);

        // ---------- reduce partials + tanh + oscillator update ----------
        {
#pragma unroll
            for (int it = 0; it < 2; it++) {
                int g = it * (GRIDN * NTH) + cta * NTH + tid;   // float4 index
                if (g < (BSZ * NHID) / 4) {
                    int b_ = g >> 7;
                    int h  = (g & 127) << 2;
                    int tl = ((b_ >> 7) << 2) + (h >> 7);
                    int ro = b_ & 127, co = h & 127;
                    const float* pp = g_part + (size_t)tl * 16384 + ro * 128 + co;
                    float4 vv[NSLICE];
#pragma unroll
                    for (int sl = 0; sl < NSLICE; sl++)
                        vv[sl] = __ldcg((const float4*)(pp + (size_t)sl * NTILE * 16384));
                    float4 s = make_float4(0.f, 0.f, 0.f, 0.f);
#pragma unroll
                    for (int sl = 0; sl < NSLICE; sl++) {
                        s.x += vv[sl].x; s.y += vv[sl].y; s.z += vv[sl].z; s.w += vv[sl].w;
                    }
                    float4 bb = *(const float4*)&bias[h];
                    float4 hz = __ldcg((const float4*)g_hz + g);
                    float4 hy = __ldcg((const float4*)g_hy + g);
                    float pre;
                    pre = tanhf(s.x + bb.x); hz.x += DT * (pre - GAMMA_C * hy.x - EPS_C * hz.x); hy.x += DT * hz.x;
                    pre = tanhf(s.y + bb.y); hz.y += DT * (pre - GAMMA_C * hy.y - EPS_C * hz.y); hy.y += DT * hz.y;
                    pre = tanhf(s.z + bb.z); hz.z += DT * (pre - GAMMA_C * hy.z - EPS_C * hz.z); hy.z += DT * hz.z;
                    pre = tanhf(s.w + bb.w); hz.w += DT * (pre - GAMMA_C * hy.w - EPS_C * hz.w); hy.w += DT * hz.w;
                    __stcg((float4*)g_hz + g, hz);
                    __stcg((float4*)g_hy + g, hy);
                }
            }
        }
        gbar(target);
    }

    // ---------- final projection: out = hy @ Wout + bout ----------
    {
        int g = cta * NTH + tid;
        if (g < BSZ * NOUT) {
            int b_ = g / NOUT;
            int o  = g - b_ * NOUT;
            float s = __ldg(&bout[o]);
            const float* hyrow = g_hy + b_ * NHID;
#pragma unroll 8
            for (int h = 0; h < NHID; h++)
                s = fmaf(__ldcg(&hyrow[h]), __ldg(&Wout[h * NOUT + o]), s);
            out[g] = s;
        }
    }
}

extern "C" void kernel_launch(void* const* d_in, const int* in_sizes, int n_in,
                              void* d_out, int out_size)
{
    const float *x = nullptr, *W = nullptr, *b = nullptr, *Wout = nullptr, *bout = nullptr;
    for (int i = 0; i < n_in; i++) {
        switch (in_sizes[i]) {
            case T_STEPS * BSZ * NINP:      x    = (const float*)d_in[i]; break;
            case (NINP + 2 * NHID) * NHID:  W    = (const float*)d_in[i]; break;
            case NHID:                      b    = (const float*)d_in[i]; break;
            case NHID * NOUT:               Wout = (const float*)d_in[i]; break;
            case NOUT:                      bout = (const float*)d_in[i]; break;
            default: break;
        }
    }
    cudaFuncSetAttribute(cornn_mma, cudaFuncAttributeMaxDynamicSharedMemorySize, SMEM_TOTAL);
    cornn_mma<<<GRIDN, NTH, SMEM_TOTAL>>>(x, W, b, Wout, bout, (float*)d_out);
}